// round 5
// baseline (speedup 1.0000x reference)
#include <cuda_runtime.h>
#include <cstdint>
#include <cstddef>
#include <math.h>

// ============================================================================
// Problem dims
// ============================================================================
#define PP   54
#define BBT  2048
#define DDIM 512

static constexpr size_t XT = (size_t)BBT * PP * DDIM;   // 56,623,104
static constexpr size_t WE = (size_t)PP * DDIM * DDIM;  // 14,155,776

static constexpr int BM = 128, BN = 256, BK = 32, STAGES = 4;
static constexpr int NTH = 256;
static constexpr int SM_STAGE = (BM + BN) * BK;            // floats per stage = 12288
static constexpr int SMEM_BYTES = SM_STAGE * STAGES * 4;   // 196608

// ============================================================================
// Device-global scratch (the allowed allocation mechanism)
// ============================================================================
__device__ __align__(16) float g_xr[XT];   // tf32-rounded x, layout [B,P,D]
__device__ __align__(16) float g_h[XT];    // gelu(h), tf32-rounded, layout [P,B,D]
__device__ __align__(16) float g_w1[WE];   // tf32-rounded W1 [P,D,D]
__device__ __align__(16) float g_w2[WE];   // tf32-rounded W2 [P,D,D]
__device__ float2 g_stats[(size_t)BBT * PP * 8];  // per-row, per-64col-slice (sum, sumsq)

// ============================================================================
// Helpers (all plain sm_80-era PTX: compiles for compute_103 without 'a')
// ============================================================================
__device__ __forceinline__ float tf32r(float x) {
    float r; asm("cvt.rna.tf32.f32 %0, %1;" : "=f"(r) : "f"(x)); return r;
}
__device__ __forceinline__ uint32_t s2u(const void* p) {
    uint32_t a;
    asm("{ .reg .u64 t; cvta.to.shared.u64 t, %1; cvt.u32.u64 %0, t; }" : "=r"(a) : "l"(p));
    return a;
}
__device__ __forceinline__ void cp16(uint32_t d, const void* s) {
    asm volatile("cp.async.cg.shared.global [%0], [%1], 16;" :: "r"(d), "l"(s));
}
__device__ __forceinline__ void cp_commit() { asm volatile("cp.async.commit_group;"); }
template <int N>
__device__ __forceinline__ void cp_wait() { asm volatile("cp.async.wait_group %0;" :: "n"(N)); }

__device__ __forceinline__ void mma8(float c[4], const float a[4], const float b[2]) {
    asm volatile(
        "mma.sync.aligned.m16n8k8.row.col.f32.tf32.tf32.f32 "
        "{%0,%1,%2,%3}, {%4,%5,%6,%7}, {%8,%9}, {%0,%1,%2,%3};"
        : "+f"(c[0]), "+f"(c[1]), "+f"(c[2]), "+f"(c[3])
        : "r"(__float_as_uint(a[0])), "r"(__float_as_uint(a[1])),
          "r"(__float_as_uint(a[2])), "r"(__float_as_uint(a[3])),
          "r"(__float_as_uint(b[0])), "r"(__float_as_uint(b[1])));
}

// ============================================================================
// Stage loader. SMEM element (row, k) lives at row*32 + (k ^ ((row&7)<<2)).
// 16B cp.async chunks: chunk' = chunk ^ (row&7)  (xor carries no bits -> exact).
// Conflict-free for both STS.128 and all fragment LDS patterns.
// ============================================================================
__device__ __forceinline__ void load_stage(uint32_t smu, int stage,
                                           const float* __restrict__ Ab, size_t Ars,
                                           const float* __restrict__ Bb,
                                           int k0, int tid) {
    uint32_t st = smu + stage * (SM_STAGE * 4);
#pragma unroll
    for (int t = 0; t < (BM * BK / 8) / NTH * 2; ++t) {  // 4 iters: 1024 chunks of A
        int idx = tid + t * NTH;
        int row = idx >> 3, seg = idx & 7;
        cp16(st + row * 128 + ((seg ^ (row & 7)) << 4),
             Ab + (size_t)row * Ars + k0 + seg * 4);
    }
    uint32_t stB = st + BM * BK * 4;
#pragma unroll
    for (int t = 0; t < 8; ++t) {                        // 2048 chunks of B
        int idx = tid + t * NTH;
        int row = idx >> 3, seg = idx & 7;
        cp16(stB + row * 128 + ((seg ^ (row & 7)) << 4),
             Bb + (size_t)row * DDIM + k0 + seg * 4);
    }
}

// ============================================================================
// Core: C[128x256] = A[128x512] * B[256x512]^T (both K-major, tf32)
// 8 warps as 2(m) x 4(n); warp tile 64x64; acc[4 mfrag][8 nfrag][4]
// ============================================================================
__device__ __forceinline__ void gemm_core(const float* __restrict__ Ab, size_t Ars,
                                          const float* __restrict__ Bb,
                                          float acc[4][8][4], float* smemf) {
    int tid = threadIdx.x;
    uint32_t smu = s2u(smemf);
#pragma unroll
    for (int s = 0; s < STAGES - 1; ++s) {
        load_stage(smu, s, Ab, Ars, Bb, s * BK, tid);
        cp_commit();
    }
    int lane = tid & 31, warp = tid >> 5;
    int wy = warp & 1, wx = warp >> 1;
    int q = lane >> 2, t4 = lane & 3;
    int sxo = q << 2;  // swizzle key: row&7 == q for every A-row/B-row this thread touches

    int rA[4], rB[8];
#pragma unroll
    for (int i = 0; i < 4; ++i) rA[i] = (wy * 64 + 16 * i + q) * BK;
#pragma unroll
    for (int j = 0; j < 8; ++j) rB[j] = BM * BK + (wx * 64 + 8 * j + q) * BK;

    int ld = STAGES - 1;
#pragma unroll 1
    for (int kc = 0; kc < DDIM / BK; ++kc) {
        cp_wait<STAGES - 2>();
        __syncthreads();  // stage kc visible to all; all warps done with stage (kc-1)
        if (ld < DDIM / BK) {
            load_stage(smu, ld & (STAGES - 1), Ab, Ars, Bb, ld * BK, tid);
            ++ld;
        }
        cp_commit();
        const float* sb = smemf + (kc & (STAGES - 1)) * SM_STAGE;
#pragma unroll
        for (int ks = 0; ks < 4; ++ks) {
            int c0 = (8 * ks + t4) ^ sxo;
            int c1 = (8 * ks + 4 + t4) ^ sxo;
            float a[4][4], b[8][2];
#pragma unroll
            for (int i = 0; i < 4; ++i) {
                a[i][0] = sb[rA[i] + c0];
                a[i][1] = sb[rA[i] + 8 * BK + c0];
                a[i][2] = sb[rA[i] + c1];
                a[i][3] = sb[rA[i] + 8 * BK + c1];
            }
#pragma unroll
            for (int j = 0; j < 8; ++j) {
                b[j][0] = sb[rB[j] + c0];
                b[j][1] = sb[rB[j] + c1];
            }
#pragma unroll
            for (int i = 0; i < 4; ++i)
#pragma unroll
                for (int j = 0; j < 8; ++j) mma8(acc[i][j], a[i], b[j]);
        }
    }
}

// ============================================================================
// GEMM1: h = gelu(x @ W1^T + b1) -> g_h [P,B,D] (tf32-rounded)
// ============================================================================
__global__ void __launch_bounds__(NTH, 1)
gemm1_kernel(const float* __restrict__ b1) {
    extern __shared__ float smemf[];
    int p = blockIdx.z, m0 = blockIdx.y * BM, n0 = blockIdx.x * BN;
    const float* Ab = g_xr + ((size_t)m0 * PP + p) * DDIM;
    const float* Bb = g_w1 + (size_t)p * DDIM * DDIM + (size_t)n0 * DDIM;

    float acc[4][8][4];
#pragma unroll
    for (int i = 0; i < 4; ++i)
#pragma unroll
        for (int j = 0; j < 8; ++j)
#pragma unroll
            for (int k = 0; k < 4; ++k) acc[i][j][k] = 0.0f;

    gemm_core(Ab, (size_t)PP * DDIM, Bb, acc, smemf);

    int lane = threadIdx.x & 31, warp = threadIdx.x >> 5;
    int wy = warp & 1, wx = warp >> 1, q = lane >> 2, t4 = lane & 3;
    const float* bias = b1 + p * DDIM + n0 + wx * 64;
#pragma unroll
    for (int i = 0; i < 4; ++i)
#pragma unroll
        for (int h = 0; h < 2; ++h) {
            int row = m0 + wy * 64 + 16 * i + q + 8 * h;
            float* hrow = g_h + ((size_t)p * BBT + row) * DDIM + n0 + wx * 64;
#pragma unroll
            for (int j = 0; j < 8; ++j) {
                int col = 8 * j + 2 * t4;
                float v0 = acc[i][j][2 * h]     + __ldg(bias + col);
                float v1 = acc[i][j][2 * h + 1] + __ldg(bias + col + 1);
                float g0 = 0.5f * v0 * (1.0f + erff(v0 * 0.70710678118654752f));
                float g1 = 0.5f * v1 * (1.0f + erff(v1 * 0.70710678118654752f));
                *reinterpret_cast<float2*>(hrow + col) = make_float2(tf32r(g0), tf32r(g1));
            }
        }
}

// ============================================================================
// GEMM2: d_out = h @ W2^T + b2 + x (unnormalized), plus per-slice LN stats
// ============================================================================
__global__ void __launch_bounds__(NTH, 1)
gemm2_kernel(const float* __restrict__ x, const float* __restrict__ b2,
             float* __restrict__ out) {
    extern __shared__ float smemf[];
    int p = blockIdx.z, m0 = blockIdx.y * BM, n0 = blockIdx.x * BN;
    const float* Ab = g_h + ((size_t)p * BBT + m0) * DDIM;
    const float* Bb = g_w2 + (size_t)p * DDIM * DDIM + (size_t)n0 * DDIM;

    float acc[4][8][4];
#pragma unroll
    for (int i = 0; i < 4; ++i)
#pragma unroll
        for (int j = 0; j < 8; ++j)
#pragma unroll
            for (int k = 0; k < 4; ++k) acc[i][j][k] = 0.0f;

    gemm_core(Ab, DDIM, Bb, acc, smemf);

    int lane = threadIdx.x & 31, warp = threadIdx.x >> 5;
    int wy = warp & 1, wx = warp >> 1, q = lane >> 2, t4 = lane & 3;
    const float* bias = b2 + p * DDIM + n0 + wx * 64;
    int slice = blockIdx.x * 4 + wx;  // 8 slices of 64 columns per output row
#pragma unroll
    for (int i = 0; i < 4; ++i)
#pragma unroll
        for (int h = 0; h < 2; ++h) {
            int row = m0 + wy * 64 + 16 * i + q + 8 * h;  // batch index b
            size_t ro = (size_t)row * PP + p;             // output row id
            const float* xr = x + ro * DDIM + n0 + wx * 64;
            float* orow = out + ro * DDIM + n0 + wx * 64;
            float s = 0.0f, ss = 0.0f;
#pragma unroll
            for (int j = 0; j < 8; ++j) {
                int col = 8 * j + 2 * t4;
                float v0 = acc[i][j][2 * h]     + __ldg(bias + col)     + __ldg(xr + col);
                float v1 = acc[i][j][2 * h + 1] + __ldg(bias + col + 1) + __ldg(xr + col + 1);
                *reinterpret_cast<float2*>(orow + col) = make_float2(v0, v1);
                s += v0 + v1;
                ss += v0 * v0 + v1 * v1;
            }
            s  += __shfl_xor_sync(0xffffffffu, s, 1);
            s  += __shfl_xor_sync(0xffffffffu, s, 2);
            ss += __shfl_xor_sync(0xffffffffu, ss, 1);
            ss += __shfl_xor_sync(0xffffffffu, ss, 2);
            if (t4 == 0) g_stats[ro * 8 + slice] = make_float2(s, ss);
        }
}

// ============================================================================
// LN finalize: normalize d_out in place using precomputed stats
// ============================================================================
__global__ void __launch_bounds__(256)
ln_kernel(float* __restrict__ out, const float* __restrict__ gamma,
          const float* __restrict__ beta) {
    int warp = threadIdx.x >> 5, lane = threadIdx.x & 31;
    size_t r = (size_t)blockIdx.x * 8 + warp;
    float s = 0.0f, ss = 0.0f;
    if (lane < 8) {
        float2 st = g_stats[r * 8 + lane];
        s = st.x; ss = st.y;
    }
    s  += __shfl_xor_sync(0xffffffffu, s, 1);
    s  += __shfl_xor_sync(0xffffffffu, s, 2);
    s  += __shfl_xor_sync(0xffffffffu, s, 4);
    ss += __shfl_xor_sync(0xffffffffu, ss, 1);
    ss += __shfl_xor_sync(0xffffffffu, ss, 2);
    ss += __shfl_xor_sync(0xffffffffu, ss, 4);
    s  = __shfl_sync(0xffffffffu, s, 0);
    ss = __shfl_sync(0xffffffffu, ss, 0);
    float mu = s * (1.0f / 512.0f);
    float rstd = rsqrtf(ss * (1.0f / 512.0f) - mu * mu + 1e-5f);

    float* row = out + r * DDIM;
#pragma unroll
    for (int c = 0; c < 4; ++c) {
        int idx = c * 128 + lane * 4;
        float4 v = *reinterpret_cast<float4*>(row + idx);
        float4 g = *reinterpret_cast<const float4*>(gamma + idx);
        float4 b = *reinterpret_cast<const float4*>(beta + idx);
        v.x = (v.x - mu) * rstd * g.x + b.x;
        v.y = (v.y - mu) * rstd * g.y + b.y;
        v.z = (v.z - mu) * rstd * g.z + b.z;
        v.w = (v.w - mu) * rstd * g.w + b.w;
        *reinterpret_cast<float4*>(row + idx) = v;
    }
}

// ============================================================================
// tf32 rounding converters
// ============================================================================
__global__ void cvt_x_kernel(const float4* __restrict__ x) {
    size_t n = XT / 4;
    size_t stride = (size_t)gridDim.x * blockDim.x;
    float4* dst = reinterpret_cast<float4*>(g_xr);
    for (size_t t = (size_t)blockIdx.x * blockDim.x + threadIdx.x; t < n; t += stride) {
        float4 v = x[t];
        v.x = tf32r(v.x); v.y = tf32r(v.y); v.z = tf32r(v.z); v.w = tf32r(v.w);
        dst[t] = v;
    }
}
__global__ void cvt_w_kernel(const float4* __restrict__ w1, const float4* __restrict__ w2) {
    size_t n = WE / 4;
    size_t stride = (size_t)gridDim.x * blockDim.x;
    float4* d1 = reinterpret_cast<float4*>(g_w1);
    float4* d2 = reinterpret_cast<float4*>(g_w2);
    for (size_t t = (size_t)blockIdx.x * blockDim.x + threadIdx.x; t < n; t += stride) {
        float4 v = w1[t];
        v.x = tf32r(v.x); v.y = tf32r(v.y); v.z = tf32r(v.z); v.w = tf32r(v.w);
        d1[t] = v;
        v = w2[t];
        v.x = tf32r(v.x); v.y = tf32r(v.y); v.z = tf32r(v.z); v.w = tf32r(v.w);
        d2[t] = v;
    }
}

// ============================================================================
// kernel_launch
// ============================================================================
extern "C" void kernel_launch(void* const* d_in, const int* in_sizes, int n_in,
                              void* d_out, int out_size) {
    const float* x     = (const float*)d_in[0];
    const float* W1    = (const float*)d_in[1];
    const float* b1    = (const float*)d_in[2];
    const float* W2    = (const float*)d_in[3];
    const float* b2    = (const float*)d_in[4];
    const float* gamma = (const float*)d_in[5];
    const float* beta  = (const float*)d_in[6];
    float* out = (float*)d_out;

    cudaFuncSetAttribute(gemm1_kernel, cudaFuncAttributeMaxDynamicSharedMemorySize, SMEM_BYTES);
    cudaFuncSetAttribute(gemm2_kernel, cudaFuncAttributeMaxDynamicSharedMemorySize, SMEM_BYTES);

    cvt_x_kernel<<<1184, 256>>>(reinterpret_cast<const float4*>(x));
    cvt_w_kernel<<<1184, 256>>>(reinterpret_cast<const float4*>(W1),
                                reinterpret_cast<const float4*>(W2));

    // x fastest = n-tile: adjacent CTAs share the A tile; one patch's W (1MB) stays L2-hot
    dim3 grid(BN == 256 ? 2 : 4, BBT / BM, PP);  // (2, 16, 54)
    gemm1_kernel<<<grid, NTH, SMEM_BYTES>>>(b1);
    gemm2_kernel<<<grid, NTH, SMEM_BYTES>>>(x, b2, out);

    ln_kernel<<<(BBT * PP) / 8, 256>>>(out, gamma, beta);
}

// round 6
// speedup vs baseline: 1.5936x; 1.5936x over previous
#include <cuda_runtime.h>
#include <cuda_fp16.h>
#include <cstdint>
#include <cstddef>
#include <math.h>

// ============================================================================
// Problem dims
// ============================================================================
#define PP   54
#define BBT  2048
#define DDIM 512

static constexpr size_t XT = (size_t)BBT * PP * DDIM;   // 56,623,104
static constexpr size_t WE = (size_t)PP * DDIM * DDIM;  // 14,155,776

static constexpr int BM = 128, BN = 128, BK = 64, STAGES = 3;  // BK in fp16 elems: 128B rows
static constexpr int NTH = 256;
static constexpr int STAGE_BYTES = (BM + BN) * BK * 2;         // 32768
static constexpr int SMEM_BYTES  = STAGE_BYTES * STAGES;       // 98304 -> 2 CTAs/SM

// ============================================================================
// Device-global scratch (the allowed allocation mechanism)
// ============================================================================
__device__ __align__(16) __half g_xh[XT];   // fp16 x, transposed to [P,B,D]
__device__ __align__(16) __half g_h[XT];    // fp16 gelu(h), [P,B,D]
__device__ __align__(16) __half g_w1[WE];   // fp16 W1 [P,D,D]
__device__ __align__(16) __half g_w2[WE];   // fp16 W2 [P,D,D]
__device__ float2 g_stats[(size_t)BBT * PP * 16];  // per-row, per-32col-slice (sum, sumsq)

// ============================================================================
// Helpers (plain sm_80-era PTX; compiles for compute_103 without 'a' features)
// ============================================================================
__device__ __forceinline__ uint32_t s2u(const void* p) {
    uint32_t a;
    asm("{ .reg .u64 t; cvta.to.shared.u64 t, %1; cvt.u32.u64 %0, t; }" : "=r"(a) : "l"(p));
    return a;
}
__device__ __forceinline__ void cp16(uint32_t d, const void* s) {
    asm volatile("cp.async.cg.shared.global [%0], [%1], 16;" :: "r"(d), "l"(s));
}
__device__ __forceinline__ void cp_commit() { asm volatile("cp.async.commit_group;"); }
template <int N>
__device__ __forceinline__ void cp_wait() { asm volatile("cp.async.wait_group %0;" :: "n"(N)); }

// fp16 MMA, fp32 accumulator: m16n8k16
__device__ __forceinline__ void mma16(float c[4], const uint32_t a[4], const uint32_t b[2]) {
    asm volatile(
        "mma.sync.aligned.m16n8k16.row.col.f32.f16.f16.f32 "
        "{%0,%1,%2,%3}, {%4,%5,%6,%7}, {%8,%9}, {%0,%1,%2,%3};"
        : "+f"(c[0]), "+f"(c[1]), "+f"(c[2]), "+f"(c[3])
        : "r"(a[0]), "r"(a[1]), "r"(a[2]), "r"(a[3]), "r"(b[0]), "r"(b[1]));
}

// ============================================================================
// Stage loader: 256 rows (128 A + 128 B) x 128B. SMEM chunk' = seg ^ (row&7).
// Conflict-free for cp.async 16B stores and all fp16 fragment LDS.32 patterns.
// Both A and B have gmem row stride DDIM halves.
// ============================================================================
__device__ __forceinline__ void load_stage(uint32_t smu, int stage,
                                           const __half* __restrict__ Ab,
                                           const __half* __restrict__ Bb,
                                           int k0, int tid) {
    uint32_t st = smu + stage * STAGE_BYTES;
#pragma unroll
    for (int t = 0; t < 4; ++t) {  // 1024 chunks of A
        int idx = tid + t * NTH;
        int r = idx >> 3, seg = idx & 7;
        cp16(st + r * 128 + ((seg ^ (r & 7)) << 4), Ab + (size_t)r * DDIM + k0 + seg * 8);
    }
    uint32_t stB = st + BM * 128;
#pragma unroll
    for (int t = 0; t < 4; ++t) {  // 1024 chunks of B
        int idx = tid + t * NTH;
        int r = idx >> 3, seg = idx & 7;
        cp16(stB + r * 128 + ((seg ^ (r & 7)) << 4), Bb + (size_t)r * DDIM + k0 + seg * 8);
    }
}

// ============================================================================
// Core: C[128x128] = A[128x512] * B[128x512]^T (fp16 K-major, fp32 acc)
// 8 warps 2(m) x 4(n); warp tile 64x32; acc[4 mfrag][4 nfrag][4]
// ============================================================================
__device__ __forceinline__ void gemm_core(const __half* __restrict__ Ab,
                                          const __half* __restrict__ Bb,
                                          float acc[4][4][4], char* smem) {
    int tid = threadIdx.x;
    uint32_t smu = s2u(smem);
    load_stage(smu, 0, Ab, Bb, 0, tid);  cp_commit();
    load_stage(smu, 1, Ab, Bb, BK, tid); cp_commit();

    int lane = tid & 31, warp = tid >> 5;
    int wy = warp & 1, wx = warp >> 1;
    int q = lane >> 2, t4 = lane & 3;

    int rA[4], rB[4];
#pragma unroll
    for (int i = 0; i < 4; ++i) rA[i] = (wy * 64 + 16 * i + q) * 128;
#pragma unroll
    for (int j = 0; j < 4; ++j) rB[j] = BM * 128 + (wx * 32 + 8 * j + q) * 128;

    int ld = 2, ls = 2, cs = 0;
#pragma unroll 1
    for (int kc = 0; kc < DDIM / BK; ++kc) {
        cp_wait<STAGES - 2>();
        __syncthreads();  // stage kc ready; all warps done with stage being overwritten
        if (ld < DDIM / BK) {
            load_stage(smu, ls, Ab, Bb, ld * BK, tid);
            ++ld; if (++ls == STAGES) ls = 0;
        }
        cp_commit();
        const char* sb = smem + cs * STAGE_BYTES;
        if (++cs == STAGES) cs = 0;
#pragma unroll
        for (int ks = 0; ks < 4; ++ks) {  // k16 slices within k64
            int c0 = (((2 * ks)     ^ q) << 4) + t4 * 4;
            int c1 = (((2 * ks + 1) ^ q) << 4) + t4 * 4;
            uint32_t a[4][4], b[4][2];
#pragma unroll
            for (int i = 0; i < 4; ++i) {
                a[i][0] = *reinterpret_cast<const uint32_t*>(sb + rA[i] + c0);
                a[i][1] = *reinterpret_cast<const uint32_t*>(sb + rA[i] + 1024 + c0);
                a[i][2] = *reinterpret_cast<const uint32_t*>(sb + rA[i] + c1);
                a[i][3] = *reinterpret_cast<const uint32_t*>(sb + rA[i] + 1024 + c1);
            }
#pragma unroll
            for (int j = 0; j < 4; ++j) {
                b[j][0] = *reinterpret_cast<const uint32_t*>(sb + rB[j] + c0);
                b[j][1] = *reinterpret_cast<const uint32_t*>(sb + rB[j] + c1);
            }
#pragma unroll
            for (int i = 0; i < 4; ++i)
#pragma unroll
                for (int j = 0; j < 4; ++j) mma16(acc[i][j], a[i], b[j]);
        }
    }
}

// ============================================================================
// GEMM1: h = gelu(x @ W1^T + b1) -> g_h [P,B,D] fp16
// ============================================================================
__global__ void __launch_bounds__(NTH, 2)
gemm1_kernel(const float* __restrict__ b1) {
    extern __shared__ char smem[];
    int p = blockIdx.z, m0 = blockIdx.y * BM, n0 = blockIdx.x * BN;
    const __half* Ab = g_xh + ((size_t)p * BBT + m0) * DDIM;
    const __half* Bb = g_w1 + (size_t)p * DDIM * DDIM + (size_t)n0 * DDIM;

    float acc[4][4][4];
#pragma unroll
    for (int i = 0; i < 4; ++i)
#pragma unroll
        for (int j = 0; j < 4; ++j)
#pragma unroll
            for (int k = 0; k < 4; ++k) acc[i][j][k] = 0.0f;

    gemm_core(Ab, Bb, acc, smem);

    int lane = threadIdx.x & 31, warp = threadIdx.x >> 5;
    int wy = warp & 1, wx = warp >> 1, q = lane >> 2, t4 = lane & 3;
    const float* bias = b1 + p * DDIM + n0 + wx * 32;
#pragma unroll
    for (int i = 0; i < 4; ++i)
#pragma unroll
        for (int h = 0; h < 2; ++h) {
            int row = m0 + wy * 64 + 16 * i + q + 8 * h;  // batch index b
            __half* hrow = g_h + ((size_t)p * BBT + row) * DDIM + n0 + wx * 32;
#pragma unroll
            for (int j = 0; j < 4; ++j) {
                int col = 8 * j + 2 * t4;
                float v0 = acc[i][j][2 * h]     + __ldg(bias + col);
                float v1 = acc[i][j][2 * h + 1] + __ldg(bias + col + 1);
                float g0 = 0.5f * v0 * (1.0f + erff(v0 * 0.70710678118654752f));
                float g1 = 0.5f * v1 * (1.0f + erff(v1 * 0.70710678118654752f));
                *reinterpret_cast<__half2*>(hrow + col) =
                    __floats2half2_rn(g0, g1);
            }
        }
}

// ============================================================================
// GEMM2: d_out = h @ W2^T + b2 + x (unnormalized), plus per-32col LN stats
// ============================================================================
__global__ void __launch_bounds__(NTH, 2)
gemm2_kernel(const float* __restrict__ x, const float* __restrict__ b2,
             float* __restrict__ out) {
    extern __shared__ char smem[];
    int p = blockIdx.z, m0 = blockIdx.y * BM, n0 = blockIdx.x * BN;
    const __half* Ab = g_h  + ((size_t)p * BBT + m0) * DDIM;
    const __half* Bb = g_w2 + (size_t)p * DDIM * DDIM + (size_t)n0 * DDIM;

    float acc[4][4][4];
#pragma unroll
    for (int i = 0; i < 4; ++i)
#pragma unroll
        for (int j = 0; j < 4; ++j)
#pragma unroll
            for (int k = 0; k < 4; ++k) acc[i][j][k] = 0.0f;

    gemm_core(Ab, Bb, acc, smem);

    int lane = threadIdx.x & 31, warp = threadIdx.x >> 5;
    int wy = warp & 1, wx = warp >> 1, q = lane >> 2, t4 = lane & 3;
    const float* bias = b2 + p * DDIM + n0 + wx * 32;
    int slice = blockIdx.x * 4 + wx;  // 16 slices of 32 cols per output row
#pragma unroll
    for (int i = 0; i < 4; ++i)
#pragma unroll
        for (int h = 0; h < 2; ++h) {
            int row = m0 + wy * 64 + 16 * i + q + 8 * h;  // batch index b
            size_t ro = (size_t)row * PP + p;             // output row id
            const float* xr = x + ro * DDIM + n0 + wx * 32;
            float* orow = out + ro * DDIM + n0 + wx * 32;
            float s = 0.0f, ss = 0.0f;
#pragma unroll
            for (int j = 0; j < 4; ++j) {
                int col = 8 * j + 2 * t4;
                float v0 = acc[i][j][2 * h]     + __ldg(bias + col)     + __ldg(xr + col);
                float v1 = acc[i][j][2 * h + 1] + __ldg(bias + col + 1) + __ldg(xr + col + 1);
                *reinterpret_cast<float2*>(orow + col) = make_float2(v0, v1);
                s += v0 + v1;
                ss += v0 * v0 + v1 * v1;
            }
            s  += __shfl_xor_sync(0xffffffffu, s, 1);
            s  += __shfl_xor_sync(0xffffffffu, s, 2);
            ss += __shfl_xor_sync(0xffffffffu, ss, 1);
            ss += __shfl_xor_sync(0xffffffffu, ss, 2);
            if (t4 == 0) g_stats[ro * 16 + slice] = make_float2(s, ss);
        }
}

// ============================================================================
// LN finalize: normalize d_out in place using precomputed stats
// ============================================================================
__global__ void __launch_bounds__(256)
ln_kernel(float* __restrict__ out, const float* __restrict__ gamma,
          const float* __restrict__ beta) {
    int warp = threadIdx.x >> 5, lane = threadIdx.x & 31;
    size_t r = (size_t)blockIdx.x * 8 + warp;
    float s = 0.0f, ss = 0.0f;
    if (lane < 16) {
        float2 st = g_stats[r * 16 + lane];
        s = st.x; ss = st.y;
    }
#pragma unroll
    for (int d = 1; d < 16; d <<= 1) {
        s  += __shfl_xor_sync(0xffffffffu, s, d);
        ss += __shfl_xor_sync(0xffffffffu, ss, d);
    }
    s  = __shfl_sync(0xffffffffu, s, 0);
    ss = __shfl_sync(0xffffffffu, ss, 0);
    float mu = s * (1.0f / 512.0f);
    float rstd = rsqrtf(ss * (1.0f / 512.0f) - mu * mu + 1e-5f);

    float* row = out + r * DDIM;
#pragma unroll
    for (int c = 0; c < 4; ++c) {
        int idx = c * 128 + lane * 4;
        float4 v = *reinterpret_cast<float4*>(row + idx);
        float4 g = *reinterpret_cast<const float4*>(gamma + idx);
        float4 b = *reinterpret_cast<const float4*>(beta + idx);
        v.x = (v.x - mu) * rstd * g.x + b.x;
        v.y = (v.y - mu) * rstd * g.y + b.y;
        v.z = (v.z - mu) * rstd * g.z + b.z;
        v.w = (v.w - mu) * rstd * g.w + b.w;
        *reinterpret_cast<float4*>(row + idx) = v;
    }
}

// ============================================================================
// Converters: fp32 -> fp16 (x also transposed [B,P,D] -> [P,B,D])
// ============================================================================
__device__ __forceinline__ uint2 pack4h(float4 v) {
    __half2 h01 = __floats2half2_rn(v.x, v.y);
    __half2 h23 = __floats2half2_rn(v.z, v.w);
    uint2 r;
    r.x = *reinterpret_cast<uint32_t*>(&h01);
    r.y = *reinterpret_cast<uint32_t*>(&h23);
    return r;
}

__global__ void cvt_x_kernel(const float4* __restrict__ x4) {
    size_t n = XT / 4;
    size_t stride = (size_t)gridDim.x * blockDim.x;
    for (size_t t = (size_t)blockIdx.x * blockDim.x + threadIdx.x; t < n; t += stride) {
        size_t d4 = t & (DDIM / 4 - 1);       // 0..127
        size_t b  = (t >> 7) & (BBT - 1);     // 0..2047
        size_t p  = t >> 18;                  // 0..53
        float4 v = x4[(b * PP + p) * (DDIM / 4) + d4];
        *reinterpret_cast<uint2*>(g_xh + (p * BBT + b) * DDIM + d4 * 4) = pack4h(v);
    }
}

__global__ void cvt_w_kernel(const float4* __restrict__ w1, const float4* __restrict__ w2) {
    size_t n = WE / 4;
    size_t stride = (size_t)gridDim.x * blockDim.x;
    for (size_t t = (size_t)blockIdx.x * blockDim.x + threadIdx.x; t < n; t += stride) {
        *reinterpret_cast<uint2*>(g_w1 + t * 4) = pack4h(w1[t]);
        *reinterpret_cast<uint2*>(g_w2 + t * 4) = pack4h(w2[t]);
    }
}

// ============================================================================
// kernel_launch
// ============================================================================
extern "C" void kernel_launch(void* const* d_in, const int* in_sizes, int n_in,
                              void* d_out, int out_size) {
    const float* x     = (const float*)d_in[0];
    const float* W1    = (const float*)d_in[1];
    const float* b1    = (const float*)d_in[2];
    const float* W2    = (const float*)d_in[3];
    const float* b2    = (const float*)d_in[4];
    const float* gamma = (const float*)d_in[5];
    const float* beta  = (const float*)d_in[6];
    float* out = (float*)d_out;

    cudaFuncSetAttribute(gemm1_kernel, cudaFuncAttributeMaxDynamicSharedMemorySize, SMEM_BYTES);
    cudaFuncSetAttribute(gemm2_kernel, cudaFuncAttributeMaxDynamicSharedMemorySize, SMEM_BYTES);

    cvt_x_kernel<<<1184, 256>>>(reinterpret_cast<const float4*>(x));
    cvt_w_kernel<<<1184, 256>>>(reinterpret_cast<const float4*>(W1),
                                reinterpret_cast<const float4*>(W2));

    // x fastest = n-tile: 4 CTAs share each A tile; one patch's W (512KB fp16) L2-hot
    dim3 grid(DDIM / BN, BBT / BM, PP);  // (4, 16, 54)
    gemm1_kernel<<<grid, NTH, SMEM_BYTES>>>(b1);
    gemm2_kernel<<<grid, NTH, SMEM_BYTES>>>(x, b2, out);

    ln_kernel<<<(BBT * PP) / 8, 256>>>(out, gamma, beta);
}

// round 7
// speedup vs baseline: 1.7532x; 1.1002x over previous
#include <cuda_runtime.h>
#include <cuda_fp16.h>
#include <cstdint>
#include <cstddef>
#include <math.h>

// ============================================================================
// Problem dims
// ============================================================================
#define PP   54
#define BBT  2048
#define DDIM 512

static constexpr size_t XT = (size_t)BBT * PP * DDIM;   // 56,623,104
static constexpr size_t WE = (size_t)PP * DDIM * DDIM;  // 14,155,776

static constexpr int BM = 128, BN = 128, BK = 64, STAGES = 3;  // BK in halves (128B rows)
static constexpr int NTH = 128;                                // 4 warps, 2x2, warp tile 64x64
static constexpr int STAGE_BYTES = (BM + BN) * BK * 2;         // 32768
static constexpr int SMEM_BYTES  = STAGE_BYTES * STAGES;       // 98304 -> 2 CTAs/SM

// ============================================================================
// Device-global scratch
// ============================================================================
__device__ __align__(16) __half g_xh[XT];   // fp16 x, transposed to [P,B,D]
__device__ __align__(16) __half g_h[XT];    // fp16 gelu(h), [P,B,D]
__device__ __align__(16) __half g_w1[WE];   // fp16 W1 [P,D,D]
__device__ __align__(16) __half g_w2[WE];   // fp16 W2 [P,D,D]
__device__ float2 g_stats[(size_t)BBT * PP * 8];  // per-row, per-64col-slice (sum, sumsq)

// ============================================================================
// PTX helpers (all pre-Hopper: compile for compute_103 without 'a' features)
// ============================================================================
__device__ __forceinline__ uint32_t s2u(const void* p) {
    uint32_t a;
    asm("{ .reg .u64 t; cvta.to.shared.u64 t, %1; cvt.u32.u64 %0, t; }" : "=r"(a) : "l"(p));
    return a;
}
__device__ __forceinline__ void cp16(uint32_t d, const void* s) {
    asm volatile("cp.async.cg.shared.global [%0], [%1], 16;" :: "r"(d), "l"(s));
}
__device__ __forceinline__ void cp_commit() { asm volatile("cp.async.commit_group;"); }
template <int N>
__device__ __forceinline__ void cp_wait() { asm volatile("cp.async.wait_group %0;" :: "n"(N)); }

__device__ __forceinline__ void ldm4(uint32_t r[4], uint32_t addr) {
    asm volatile("ldmatrix.sync.aligned.m8n8.x4.shared.b16 {%0,%1,%2,%3}, [%4];"
                 : "=r"(r[0]), "=r"(r[1]), "=r"(r[2]), "=r"(r[3]) : "r"(addr));
}

// fp16 MMA, fp32 accumulator: m16n8k16
__device__ __forceinline__ void mma16(float c[4], const uint32_t a[4], const uint32_t b[2]) {
    asm volatile(
        "mma.sync.aligned.m16n8k16.row.col.f32.f16.f16.f32 "
        "{%0,%1,%2,%3}, {%4,%5,%6,%7}, {%8,%9}, {%0,%1,%2,%3};"
        : "+f"(c[0]), "+f"(c[1]), "+f"(c[2]), "+f"(c[3])
        : "r"(a[0]), "r"(a[1]), "r"(a[2]), "r"(a[3]), "r"(b[0]), "r"(b[1]));
}

// ============================================================================
// Stage loader: 256 rows (128 A + 128 B) x 128B. SMEM 16B-chunk' = seg ^ (row&7).
// Conflict-free for cp.async 16B stores and for ldmatrix fragment reads.
// ============================================================================
__device__ __forceinline__ void load_stage(uint32_t smu, int stage,
                                           const __half* __restrict__ Ab,
                                           const __half* __restrict__ Bb,
                                           int k0, int tid) {
    uint32_t st = smu + stage * STAGE_BYTES;
#pragma unroll
    for (int t = 0; t < 8; ++t) {  // 1024 chunks of A
        int idx = tid + t * NTH;
        int r = idx >> 3, seg = idx & 7;
        cp16(st + r * 128 + ((seg ^ (r & 7)) << 4), Ab + (size_t)r * DDIM + k0 + seg * 8);
    }
    uint32_t stB = st + BM * 128;
#pragma unroll
    for (int t = 0; t < 8; ++t) {  // 1024 chunks of B
        int idx = tid + t * NTH;
        int r = idx >> 3, seg = idx & 7;
        cp16(stB + r * 128 + ((seg ^ (r & 7)) << 4), Bb + (size_t)r * DDIM + k0 + seg * 8);
    }
}

// ============================================================================
// Core: C[128x128] = A[128x512] * B[128x512]^T (fp16 K-major, fp32 acc)
// 4 warps 2(m) x 2(n); warp tile 64x64; acc[4 mfrag][8 nfrag][4]
// ============================================================================
__device__ __forceinline__ void gemm_core(const __half* __restrict__ Ab,
                                          const __half* __restrict__ Bb,
                                          float acc[4][8][4], char* smem) {
    int tid = threadIdx.x;
    uint32_t smu = s2u(smem);
    load_stage(smu, 0, Ab, Bb, 0, tid);  cp_commit();
    load_stage(smu, 1, Ab, Bb, BK, tid); cp_commit();

    int lane = tid & 31, warp = tid >> 5;
    int wy = warp & 1, wx = warp >> 1;
    int lane7 = lane & 7, sub = lane >> 3;
    int aSel = sub >> 1, bSel = sub & 1;  // which 16B seg (lo/hi of k16) this thread fetches

    // ldmatrix per-thread row bases. row&7 == lane7 for every fragment row.
    uint32_t aBase[4], bBase[4];
#pragma unroll
    for (int i = 0; i < 4; ++i)
        aBase[i] = (uint32_t)(wy * 64 + 16 * i + lane7 + 8 * (sub & 1)) * 128;
#pragma unroll
    for (int jp = 0; jp < 4; ++jp)
        bBase[jp] = (uint32_t)(BM * 128) +
                    (uint32_t)(wx * 64 + 16 * jp + 8 * (sub >> 1) + lane7) * 128;

    int ld = 2, ls = 2, cs = 0;
#pragma unroll 1
    for (int kc = 0; kc < DDIM / BK; ++kc) {
        cp_wait<STAGES - 2>();
        __syncthreads();  // stage kc ready; all warps done with stage being overwritten
        if (ld < DDIM / BK) {
            load_stage(smu, ls, Ab, Bb, ld * BK, tid);
            ++ld; if (++ls == STAGES) ls = 0;
        }
        cp_commit();
        uint32_t sbu = smu + cs * STAGE_BYTES;
        if (++cs == STAGES) cs = 0;
#pragma unroll
        for (int ks = 0; ks < 4; ++ks) {  // k16 slices within k64
            uint32_t swA = (uint32_t)(((2 * ks + aSel) ^ lane7) << 4);
            uint32_t swB = (uint32_t)(((2 * ks + bSel) ^ lane7) << 4);
            uint32_t a[4][4], b[4][4];  // b[jp] = frags {2jp:[0,1], 2jp+1:[2,3]}
#pragma unroll
            for (int i = 0; i < 4; ++i) ldm4(a[i], sbu + aBase[i] + swA);
#pragma unroll
            for (int jp = 0; jp < 4; ++jp) ldm4(b[jp], sbu + bBase[jp] + swB);
#pragma unroll
            for (int i = 0; i < 4; ++i)
#pragma unroll
                for (int j = 0; j < 8; ++j)
                    mma16(acc[i][j], a[i], &b[j >> 1][(j & 1) * 2]);
        }
    }
}

// ============================================================================
// GEMM1: h = gelu(x @ W1^T + b1) -> g_h [P,B,D] fp16
// ============================================================================
__global__ void __launch_bounds__(NTH, 2)
gemm1_kernel(const float* __restrict__ b1) {
    extern __shared__ char smem[];
    int p = blockIdx.z, m0 = blockIdx.y * BM, n0 = blockIdx.x * BN;
    const __half* Ab = g_xh + ((size_t)p * BBT + m0) * DDIM;
    const __half* Bb = g_w1 + (size_t)p * DDIM * DDIM + (size_t)n0 * DDIM;

    float acc[4][8][4];
#pragma unroll
    for (int i = 0; i < 4; ++i)
#pragma unroll
        for (int j = 0; j < 8; ++j)
#pragma unroll
            for (int k = 0; k < 4; ++k) acc[i][j][k] = 0.0f;

    gemm_core(Ab, Bb, acc, smem);

    int lane = threadIdx.x & 31, warp = threadIdx.x >> 5;
    int wy = warp & 1, wx = warp >> 1, q = lane >> 2, t4 = lane & 3;
    const float* bias = b1 + p * DDIM + n0 + wx * 64;
#pragma unroll
    for (int i = 0; i < 4; ++i)
#pragma unroll
        for (int h = 0; h < 2; ++h) {
            int row = m0 + wy * 64 + 16 * i + q + 8 * h;  // batch index b
            __half* hrow = g_h + ((size_t)p * BBT + row) * DDIM + n0 + wx * 64;
#pragma unroll
            for (int j = 0; j < 8; ++j) {
                int col = 8 * j + 2 * t4;
                float v0 = acc[i][j][2 * h]     + __ldg(bias + col);
                float v1 = acc[i][j][2 * h + 1] + __ldg(bias + col + 1);
                float g0 = 0.5f * v0 * (1.0f + erff(v0 * 0.70710678118654752f));
                float g1 = 0.5f * v1 * (1.0f + erff(v1 * 0.70710678118654752f));
                *reinterpret_cast<__half2*>(hrow + col) = __floats2half2_rn(g0, g1);
            }
        }
}

// ============================================================================
// GEMM2: d_out = h @ W2^T + b2 + x (unnormalized), plus per-64col LN stats
// ============================================================================
__global__ void __launch_bounds__(NTH, 2)
gemm2_kernel(const float* __restrict__ x, const float* __restrict__ b2,
             float* __restrict__ out) {
    extern __shared__ char smem[];
    int p = blockIdx.z, m0 = blockIdx.y * BM, n0 = blockIdx.x * BN;
    const __half* Ab = g_h  + ((size_t)p * BBT + m0) * DDIM;
    const __half* Bb = g_w2 + (size_t)p * DDIM * DDIM + (size_t)n0 * DDIM;

    float acc[4][8][4];
#pragma unroll
    for (int i = 0; i < 4; ++i)
#pragma unroll
        for (int j = 0; j < 8; ++j)
#pragma unroll
            for (int k = 0; k < 4; ++k) acc[i][j][k] = 0.0f;

    gemm_core(Ab, Bb, acc, smem);

    int lane = threadIdx.x & 31, warp = threadIdx.x >> 5;
    int wy = warp & 1, wx = warp >> 1, q = lane >> 2, t4 = lane & 3;
    const float* bias = b2 + p * DDIM + n0 + wx * 64;
    int slice = blockIdx.x * 2 + wx;  // 8 slices of 64 cols per output row
#pragma unroll
    for (int i = 0; i < 4; ++i)
#pragma unroll
        for (int h = 0; h < 2; ++h) {
            int row = m0 + wy * 64 + 16 * i + q + 8 * h;  // batch index b
            size_t ro = (size_t)row * PP + p;             // output row id
            const float* xr = x + ro * DDIM + n0 + wx * 64;
            float* orow = out + ro * DDIM + n0 + wx * 64;
            float s = 0.0f, ss = 0.0f;
#pragma unroll
            for (int j = 0; j < 8; ++j) {
                int col = 8 * j + 2 * t4;
                float v0 = acc[i][j][2 * h]     + __ldg(bias + col)     + __ldg(xr + col);
                float v1 = acc[i][j][2 * h + 1] + __ldg(bias + col + 1) + __ldg(xr + col + 1);
                *reinterpret_cast<float2*>(orow + col) = make_float2(v0, v1);
                s += v0 + v1;
                ss += v0 * v0 + v1 * v1;
            }
            s  += __shfl_xor_sync(0xffffffffu, s, 1);
            s  += __shfl_xor_sync(0xffffffffu, s, 2);
            ss += __shfl_xor_sync(0xffffffffu, ss, 1);
            ss += __shfl_xor_sync(0xffffffffu, ss, 2);
            if (t4 == 0) g_stats[ro * 8 + slice] = make_float2(s, ss);
        }
}

// ============================================================================
// LN finalize: normalize d_out in place using precomputed stats
// ============================================================================
__global__ void __launch_bounds__(256)
ln_kernel(float* __restrict__ out, const float* __restrict__ gamma,
          const float* __restrict__ beta) {
    int warp = threadIdx.x >> 5, lane = threadIdx.x & 31;
    size_t r = (size_t)blockIdx.x * 8 + warp;
    float s = 0.0f, ss = 0.0f;
    if (lane < 8) {
        float2 st = g_stats[r * 8 + lane];
        s = st.x; ss = st.y;
    }
#pragma unroll
    for (int d = 1; d < 8; d <<= 1) {
        s  += __shfl_xor_sync(0xffffffffu, s, d);
        ss += __shfl_xor_sync(0xffffffffu, ss, d);
    }
    s  = __shfl_sync(0xffffffffu, s, 0);
    ss = __shfl_sync(0xffffffffu, ss, 0);
    float mu = s * (1.0f / 512.0f);
    float rstd = rsqrtf(ss * (1.0f / 512.0f) - mu * mu + 1e-5f);

    float* row = out + r * DDIM;
#pragma unroll
    for (int c = 0; c < 4; ++c) {
        int idx = c * 128 + lane * 4;
        float4 v = *reinterpret_cast<float4*>(row + idx);
        float4 g = *reinterpret_cast<const float4*>(gamma + idx);
        float4 b = *reinterpret_cast<const float4*>(beta + idx);
        v.x = (v.x - mu) * rstd * g.x + b.x;
        v.y = (v.y - mu) * rstd * g.y + b.y;
        v.z = (v.z - mu) * rstd * g.z + b.z;
        v.w = (v.w - mu) * rstd * g.w + b.w;
        *reinterpret_cast<float4*>(row + idx) = v;
    }
}

// ============================================================================
// Converters: fp32 -> fp16 (x also transposed [B,P,D] -> [P,B,D])
// ============================================================================
__device__ __forceinline__ uint2 pack4h(float4 v) {
    __half2 h01 = __floats2half2_rn(v.x, v.y);
    __half2 h23 = __floats2half2_rn(v.z, v.w);
    uint2 r;
    r.x = *reinterpret_cast<uint32_t*>(&h01);
    r.y = *reinterpret_cast<uint32_t*>(&h23);
    return r;
}

__global__ void cvt_x_kernel(const float4* __restrict__ x4) {
    size_t n = XT / 4;
    size_t stride = (size_t)gridDim.x * blockDim.x;
    for (size_t t = (size_t)blockIdx.x * blockDim.x + threadIdx.x; t < n; t += stride) {
        size_t d4 = t & (DDIM / 4 - 1);       // 0..127
        size_t b  = (t >> 7) & (BBT - 1);     // 0..2047
        size_t p  = t >> 18;                  // 0..53
        float4 v = x4[(b * PP + p) * (DDIM / 4) + d4];
        *reinterpret_cast<uint2*>(g_xh + (p * BBT + b) * DDIM + d4 * 4) = pack4h(v);
    }
}

__global__ void cvt_w_kernel(const float4* __restrict__ w1, const float4* __restrict__ w2) {
    size_t n = WE / 4;
    size_t stride = (size_t)gridDim.x * blockDim.x;
    for (size_t t = (size_t)blockIdx.x * blockDim.x + threadIdx.x; t < n; t += stride) {
        *reinterpret_cast<uint2*>(g_w1 + t * 4) = pack4h(w1[t]);
        *reinterpret_cast<uint2*>(g_w2 + t * 4) = pack4h(w2[t]);
    }
}

// ============================================================================
// kernel_launch
// ============================================================================
extern "C" void kernel_launch(void* const* d_in, const int* in_sizes, int n_in,
                              void* d_out, int out_size) {
    const float* x     = (const float*)d_in[0];
    const float* W1    = (const float*)d_in[1];
    const float* b1    = (const float*)d_in[2];
    const float* W2    = (const float*)d_in[3];
    const float* b2    = (const float*)d_in[4];
    const float* gamma = (const float*)d_in[5];
    const float* beta  = (const float*)d_in[6];
    float* out = (float*)d_out;

    cudaFuncSetAttribute(gemm1_kernel, cudaFuncAttributeMaxDynamicSharedMemorySize, SMEM_BYTES);
    cudaFuncSetAttribute(gemm2_kernel, cudaFuncAttributeMaxDynamicSharedMemorySize, SMEM_BYTES);

    cvt_x_kernel<<<1184, 256>>>(reinterpret_cast<const float4*>(x));
    cvt_w_kernel<<<1184, 256>>>(reinterpret_cast<const float4*>(W1),
                                reinterpret_cast<const float4*>(W2));

    // x fastest = n-tile: 4 CTAs share each A tile; one patch's W (512KB fp16) L2-hot
    dim3 grid(DDIM / BN, BBT / BM, PP);  // (4, 16, 54)
    gemm1_kernel<<<grid, NTH, SMEM_BYTES>>>(b1);
    gemm2_kernel<<<grid, NTH, SMEM_BYTES>>>(x, b2, out);

    ln_kernel<<<(BBT * PP) / 8, 256>>>(out, gamma, beta);
}

// round 8
// speedup vs baseline: 1.7535x; 1.0002x over previous
#include <cuda_runtime.h>
#include <cuda_fp16.h>
#include <cstdint>
#include <cstddef>
#include <math.h>

// ============================================================================
// Problem dims
// ============================================================================
#define PP   54
#define BBT  2048
#define DDIM 512

static constexpr size_t XT = (size_t)BBT * PP * DDIM;   // 56,623,104
static constexpr size_t WE = (size_t)PP * DDIM * DDIM;  // 14,155,776

static constexpr int BM = 128, BN = 128, BK = 64, STAGES = 3;  // BK in halves (128B rows)
static constexpr int NTH = 128;                                // 4 warps, 2x2, warp tile 64x64
static constexpr int STAGE_BYTES = (BM + BN) * BK * 2;         // 32768
static constexpr int SMEM_BYTES  = STAGE_BYTES * STAGES;       // 98304 -> 2 CTAs/SM

// ============================================================================
// Device-global scratch
// ============================================================================
__device__ __align__(16) __half g_xh[XT];   // fp16 x, transposed to [P,B,D]
__device__ __align__(16) __half g_h[XT];    // fp16 gelu(h), [P,B,D]
__device__ __align__(16) __half g_w1[WE];   // fp16 W1 [P,D,D]
__device__ __align__(16) __half g_w2[WE];   // fp16 W2 [P,D,D]
__device__ float2 g_stats[(size_t)BBT * PP * 8];  // per-row, per-64col-slice (sum, sumsq)

// ============================================================================
// PTX helpers (all pre-Hopper: compile for compute_103 without 'a' features)
// ============================================================================
__device__ __forceinline__ uint32_t s2u(const void* p) {
    uint32_t a;
    asm("{ .reg .u64 t; cvta.to.shared.u64 t, %1; cvt.u32.u64 %0, t; }" : "=r"(a) : "l"(p));
    return a;
}
__device__ __forceinline__ void cp16(uint32_t d, const void* s) {
    asm volatile("cp.async.cg.shared.global [%0], [%1], 16;" :: "r"(d), "l"(s));
}
__device__ __forceinline__ void cp_commit() { asm volatile("cp.async.commit_group;"); }
template <int N>
__device__ __forceinline__ void cp_wait() { asm volatile("cp.async.wait_group %0;" :: "n"(N)); }

__device__ __forceinline__ void ldm4(uint32_t r[4], uint32_t addr) {
    asm volatile("ldmatrix.sync.aligned.m8n8.x4.shared.b16 {%0,%1,%2,%3}, [%4];"
                 : "=r"(r[0]), "=r"(r[1]), "=r"(r[2]), "=r"(r[3]) : "r"(addr));
}

// fp16 MMA, fp32 accumulator: m16n8k16
__device__ __forceinline__ void mma16(float c[4], const uint32_t a[4], const uint32_t b[2]) {
    asm volatile(
        "mma.sync.aligned.m16n8k16.row.col.f32.f16.f16.f32 "
        "{%0,%1,%2,%3}, {%4,%5,%6,%7}, {%8,%9}, {%0,%1,%2,%3};"
        : "+f"(c[0]), "+f"(c[1]), "+f"(c[2]), "+f"(c[3])
        : "r"(a[0]), "r"(a[1]), "r"(a[2]), "r"(a[3]), "r"(b[0]), "r"(b[1]));
}

// ============================================================================
// Core: C[128x128] = A[128x512] * B[128x512]^T (fp16 K-major, fp32 acc)
// 4 warps 2(m) x 2(n); warp tile 64x64; acc[4 mfrag][8 nfrag][4]
//
// Load addressing is fully hoisted: with 128 threads, each thread owns 8 A
// chunks + 8 B chunks at rows (tid>>3) + 16t, seg = tid&7 fixed. The swizzle
// key (seg ^ (row&7)) is per-thread constant, so every address is base + t*K.
// Fragments are register double-buffered across k16 slices (ldm for ks+1
// overlaps the 32 MMAs of ks).
// ============================================================================
__device__ __forceinline__ void gemm_core(const __half* __restrict__ Ab,
                                          const __half* __restrict__ Bb,
                                          float acc[4][8][4], char* smem) {
    int tid = threadIdx.x;
    uint32_t smu = s2u(smem);
    int r0 = tid >> 3, seg = tid & 7;

    const __half* aPtr = Ab + (size_t)r0 * DDIM + seg * 8;
    const __half* bPtr = Bb + (size_t)r0 * DDIM + seg * 8;
    uint32_t dstA = smu + (uint32_t)(r0 * 128 + ((seg ^ (r0 & 7)) << 4));
    uint32_t dstB = dstA + BM * 128;

    auto load = [&](int stage, int k0) {
        uint32_t so = (uint32_t)stage * STAGE_BYTES;
#pragma unroll
        for (int t = 0; t < 8; ++t)
            cp16(dstA + so + t * 2048, aPtr + k0 + (size_t)t * 16 * DDIM);
#pragma unroll
        for (int t = 0; t < 8; ++t)
            cp16(dstB + so + t * 2048, bPtr + k0 + (size_t)t * 16 * DDIM);
    };

    load(0, 0);  cp_commit();
    load(1, BK); cp_commit();

    int lane = tid & 31, warp = tid >> 5;
    int wy = warp & 1, wx = warp >> 1;
    int lane7 = lane & 7, sub = lane >> 3;
    int aSel = sub >> 1, bSel = sub & 1;  // which 16B seg (lo/hi of k16) this thread fetches

    // ldmatrix per-thread row bases. row&7 == lane7 for every fragment row.
    uint32_t aBase[4], bBase[4];
#pragma unroll
    for (int i = 0; i < 4; ++i)
        aBase[i] = (uint32_t)(wy * 64 + 16 * i + lane7 + 8 * (sub & 1)) * 128;
#pragma unroll
    for (int jp = 0; jp < 4; ++jp)
        bBase[jp] = (uint32_t)(BM * 128) +
                    (uint32_t)(wx * 64 + 16 * jp + 8 * (sub >> 1) + lane7) * 128;

    int ld = 2, ls = 2, cs = 0;
#pragma unroll 1
    for (int kc = 0; kc < DDIM / BK; ++kc) {
        cp_wait<STAGES - 2>();
        __syncthreads();  // stage kc ready; all warps done with stage being overwritten
        if (ld < DDIM / BK) {
            load(ls, ld * BK);
            ++ld; if (++ls == STAGES) ls = 0;
        }
        cp_commit();
        uint32_t sbu = smu + cs * STAGE_BYTES;
        if (++cs == STAGES) cs = 0;

        uint32_t a[2][4][4], b[2][4][4];
        // prologue: fragments for ks = 0
        {
            uint32_t swA = (uint32_t)((aSel ^ lane7) << 4);
            uint32_t swB = (uint32_t)((bSel ^ lane7) << 4);
#pragma unroll
            for (int i = 0; i < 4; ++i) ldm4(a[0][i], sbu + aBase[i] + swA);
#pragma unroll
            for (int jp = 0; jp < 4; ++jp) ldm4(b[0][jp], sbu + bBase[jp] + swB);
        }
#pragma unroll
        for (int ks = 0; ks < 4; ++ks) {
            int cb = ks & 1, nb = cb ^ 1;
            if (ks < 3) {  // prefetch ks+1 fragments; overlaps the MMA block below
                uint32_t swA = (uint32_t)(((2 * (ks + 1) + aSel) ^ lane7) << 4);
                uint32_t swB = (uint32_t)(((2 * (ks + 1) + bSel) ^ lane7) << 4);
#pragma unroll
                for (int i = 0; i < 4; ++i) ldm4(a[nb][i], sbu + aBase[i] + swA);
#pragma unroll
                for (int jp = 0; jp < 4; ++jp) ldm4(b[nb][jp], sbu + bBase[jp] + swB);
            }
#pragma unroll
            for (int i = 0; i < 4; ++i)
#pragma unroll
                for (int j = 0; j < 8; ++j)
                    mma16(acc[i][j], a[cb][i], &b[cb][j >> 1][(j & 1) * 2]);
        }
    }
}

// ============================================================================
// GEMM1: h = gelu(x @ W1^T + b1) -> g_h [P,B,D] fp16
// ============================================================================
__global__ void __launch_bounds__(NTH, 2)
gemm1_kernel(const float* __restrict__ b1) {
    extern __shared__ char smem[];
    int p = blockIdx.z, m0 = blockIdx.y * BM, n0 = blockIdx.x * BN;
    const __half* Ab = g_xh + ((size_t)p * BBT + m0) * DDIM;
    const __half* Bb = g_w1 + (size_t)p * DDIM * DDIM + (size_t)n0 * DDIM;

    float acc[4][8][4];
#pragma unroll
    for (int i = 0; i < 4; ++i)
#pragma unroll
        for (int j = 0; j < 8; ++j)
#pragma unroll
            for (int k = 0; k < 4; ++k) acc[i][j][k] = 0.0f;

    gemm_core(Ab, Bb, acc, smem);

    int lane = threadIdx.x & 31, warp = threadIdx.x >> 5;
    int wy = warp & 1, wx = warp >> 1, q = lane >> 2, t4 = lane & 3;
    const float* bias = b1 + p * DDIM + n0 + wx * 64;
#pragma unroll
    for (int i = 0; i < 4; ++i)
#pragma unroll
        for (int h = 0; h < 2; ++h) {
            int row = m0 + wy * 64 + 16 * i + q + 8 * h;  // batch index b
            __half* hrow = g_h + ((size_t)p * BBT + row) * DDIM + n0 + wx * 64;
#pragma unroll
            for (int j = 0; j < 8; ++j) {
                int col = 8 * j + 2 * t4;
                float v0 = acc[i][j][2 * h]     + __ldg(bias + col);
                float v1 = acc[i][j][2 * h + 1] + __ldg(bias + col + 1);
                float g0 = 0.5f * v0 * (1.0f + erff(v0 * 0.70710678118654752f));
                float g1 = 0.5f * v1 * (1.0f + erff(v1 * 0.70710678118654752f));
                *reinterpret_cast<__half2*>(hrow + col) = __floats2half2_rn(g0, g1);
            }
        }
}

// ============================================================================
// GEMM2: d_out = h @ W2^T + b2 + x (unnormalized), plus per-64col LN stats
// ============================================================================
__global__ void __launch_bounds__(NTH, 2)
gemm2_kernel(const float* __restrict__ x, const float* __restrict__ b2,
             float* __restrict__ out) {
    extern __shared__ char smem[];
    int p = blockIdx.z, m0 = blockIdx.y * BM, n0 = blockIdx.x * BN;
    const __half* Ab = g_h  + ((size_t)p * BBT + m0) * DDIM;
    const __half* Bb = g_w2 + (size_t)p * DDIM * DDIM + (size_t)n0 * DDIM;

    float acc[4][8][4];
#pragma unroll
    for (int i = 0; i < 4; ++i)
#pragma unroll
        for (int j = 0; j < 8; ++j)
#pragma unroll
            for (int k = 0; k < 4; ++k) acc[i][j][k] = 0.0f;

    gemm_core(Ab, Bb, acc, smem);

    int lane = threadIdx.x & 31, warp = threadIdx.x >> 5;
    int wy = warp & 1, wx = warp >> 1, q = lane >> 2, t4 = lane & 3;
    const float* bias = b2 + p * DDIM + n0 + wx * 64;
    int slice = blockIdx.x * 2 + wx;  // 8 slices of 64 cols per output row
#pragma unroll
    for (int i = 0; i < 4; ++i)
#pragma unroll
        for (int h = 0; h < 2; ++h) {
            int row = m0 + wy * 64 + 16 * i + q + 8 * h;  // batch index b
            size_t ro = (size_t)row * PP + p;             // output row id
            const float* xr = x + ro * DDIM + n0 + wx * 64;
            float* orow = out + ro * DDIM + n0 + wx * 64;
            float s = 0.0f, ss = 0.0f;
#pragma unroll
            for (int j = 0; j < 8; ++j) {
                int col = 8 * j + 2 * t4;
                float v0 = acc[i][j][2 * h]     + __ldg(bias + col)     + __ldg(xr + col);
                float v1 = acc[i][j][2 * h + 1] + __ldg(bias + col + 1) + __ldg(xr + col + 1);
                *reinterpret_cast<float2*>(orow + col) = make_float2(v0, v1);
                s += v0 + v1;
                ss += v0 * v0 + v1 * v1;
            }
            s  += __shfl_xor_sync(0xffffffffu, s, 1);
            s  += __shfl_xor_sync(0xffffffffu, s, 2);
            ss += __shfl_xor_sync(0xffffffffu, ss, 1);
            ss += __shfl_xor_sync(0xffffffffu, ss, 2);
            if (t4 == 0) g_stats[ro * 8 + slice] = make_float2(s, ss);
        }
}

// ============================================================================
// LN finalize: normalize d_out in place using precomputed stats
// ============================================================================
__global__ void __launch_bounds__(256)
ln_kernel(float* __restrict__ out, const float* __restrict__ gamma,
          const float* __restrict__ beta) {
    int warp = threadIdx.x >> 5, lane = threadIdx.x & 31;
    size_t r = (size_t)blockIdx.x * 8 + warp;
    float s = 0.0f, ss = 0.0f;
    if (lane < 8) {
        float2 st = g_stats[r * 8 + lane];
        s = st.x; ss = st.y;
    }
#pragma unroll
    for (int d = 1; d < 8; d <<= 1) {
        s  += __shfl_xor_sync(0xffffffffu, s, d);
        ss += __shfl_xor_sync(0xffffffffu, ss, d);
    }
    s  = __shfl_sync(0xffffffffu, s, 0);
    ss = __shfl_sync(0xffffffffu, ss, 0);
    float mu = s * (1.0f / 512.0f);
    float rstd = rsqrtf(ss * (1.0f / 512.0f) - mu * mu + 1e-5f);

    float* row = out + r * DDIM;
#pragma unroll
    for (int c = 0; c < 4; ++c) {
        int idx = c * 128 + lane * 4;
        float4 v = *reinterpret_cast<float4*>(row + idx);
        float4 g = *reinterpret_cast<const float4*>(gamma + idx);
        float4 b = *reinterpret_cast<const float4*>(beta + idx);
        v.x = (v.x - mu) * rstd * g.x + b.x;
        v.y = (v.y - mu) * rstd * g.y + b.y;
        v.z = (v.z - mu) * rstd * g.z + b.z;
        v.w = (v.w - mu) * rstd * g.w + b.w;
        *reinterpret_cast<float4*>(row + idx) = v;
    }
}

// ============================================================================
// Converters: fp32 -> fp16 (x also transposed [B,P,D] -> [P,B,D])
// ============================================================================
__device__ __forceinline__ uint2 pack4h(float4 v) {
    __half2 h01 = __floats2half2_rn(v.x, v.y);
    __half2 h23 = __floats2half2_rn(v.z, v.w);
    uint2 r;
    r.x = *reinterpret_cast<uint32_t*>(&h01);
    r.y = *reinterpret_cast<uint32_t*>(&h23);
    return r;
}

__global__ void cvt_x_kernel(const float4* __restrict__ x4) {
    size_t n = XT / 4;
    size_t stride = (size_t)gridDim.x * blockDim.x;
    for (size_t t = (size_t)blockIdx.x * blockDim.x + threadIdx.x; t < n; t += stride) {
        size_t d4 = t & (DDIM / 4 - 1);       // 0..127
        size_t b  = (t >> 7) & (BBT - 1);     // 0..2047
        size_t p  = t >> 18;                  // 0..53
        float4 v = x4[(b * PP + p) * (DDIM / 4) + d4];
        *reinterpret_cast<uint2*>(g_xh + (p * BBT + b) * DDIM + d4 * 4) = pack4h(v);
    }
}

__global__ void cvt_w_kernel(const float4* __restrict__ w1, const float4* __restrict__ w2) {
    size_t n = WE / 4;
    size_t stride = (size_t)gridDim.x * blockDim.x;
    for (size_t t = (size_t)blockIdx.x * blockDim.x + threadIdx.x; t < n; t += stride) {
        *reinterpret_cast<uint2*>(g_w1 + t * 4) = pack4h(w1[t]);
        *reinterpret_cast<uint2*>(g_w2 + t * 4) = pack4h(w2[t]);
    }
}

// ============================================================================
// kernel_launch
// ============================================================================
extern "C" void kernel_launch(void* const* d_in, const int* in_sizes, int n_in,
                              void* d_out, int out_size) {
    const float* x     = (const float*)d_in[0];
    const float* W1    = (const float*)d_in[1];
    const float* b1    = (const float*)d_in[2];
    const float* W2    = (const float*)d_in[3];
    const float* b2    = (const float*)d_in[4];
    const float* gamma = (const float*)d_in[5];
    const float* beta  = (const float*)d_in[6];
    float* out = (float*)d_out;

    cudaFuncSetAttribute(gemm1_kernel, cudaFuncAttributeMaxDynamicSharedMemorySize, SMEM_BYTES);
    cudaFuncSetAttribute(gemm2_kernel, cudaFuncAttributeMaxDynamicSharedMemorySize, SMEM_BYTES);

    cvt_x_kernel<<<1184, 256>>>(reinterpret_cast<const float4*>(x));
    cvt_w_kernel<<<1184, 256>>>(reinterpret_cast<const float4*>(W1),
                                reinterpret_cast<const float4*>(W2));

    // x fastest = n-tile: 4 CTAs share each A tile; one patch's W (512KB fp16) L2-hot
    dim3 grid(DDIM / BN, BBT / BM, PP);  // (4, 16, 54)
    gemm1_kernel<<<grid, NTH, SMEM_BYTES>>>(b1);
    gemm2_kernel<<<grid, NTH, SMEM_BYTES>>>(x, b2, out);

    ln_kernel<<<(BBT * PP) / 8, 256>>>(out, gamma, beta);
}